// round 1
// baseline (speedup 1.0000x reference)
#include <cuda_runtime.h>

// ---------------------------------------------------------------------------
// AlexNet (CIFAR variant) forward, B=256, fp32.
// Pipeline: conv1 fused (conv+relu+pool) -> [im2col + SGEMM(+bias+relu)] x4
//           -> maxpools -> FC SGEMMs.
// Scratch via __device__ globals (no allocation allowed).
// ---------------------------------------------------------------------------

#define NIMG 256

// Max intermediate activation: conv2 pre-pool = 256*192*16*16 = 12,582,912 floats
__device__ float g_act0[NIMG * 192 * 16 * 16];
__device__ float g_act1[NIMG * 192 * 16 * 16];
// Max im2col: conv2 K=64*25=1600, N=256*16*16=65536 -> 104,857,600 floats (~420MB)
__device__ float g_col[1600 * 65536];

// ---------------------------------------------------------------------------
// conv1: 3x3, C_in=3, pad=1, 32x32 -> relu -> maxpool2 -> [256,64,16,16]
// block = (oc, n), 256 threads = 16x16 pooled pixels
// ---------------------------------------------------------------------------
__global__ __launch_bounds__(256) void conv1_pool_kernel(
    const float* __restrict__ x, const float* __restrict__ w,
    const float* __restrict__ b, float* __restrict__ out) {
    __shared__ float xs[3 * 32 * 32];
    __shared__ float ws[27];
    const int oc = blockIdx.x;
    const int n = blockIdx.y;
    const int tid = threadIdx.x;

    const float* xn = x + (long long)n * 3 * 32 * 32;
    for (int i = tid; i < 3 * 32 * 32; i += 256) xs[i] = xn[i];
    if (tid < 27) ws[tid] = w[oc * 27 + tid];
    __syncthreads();

    const float bias = b[oc];
    const int px = tid & 15, py = tid >> 4;
    float m = -1e30f;
#pragma unroll
    for (int dy = 0; dy < 2; dy++) {
#pragma unroll
        for (int dx = 0; dx < 2; dx++) {
            const int oy = 2 * py + dy, ox = 2 * px + dx;
            float sum = bias;
#pragma unroll
            for (int ci = 0; ci < 3; ci++) {
#pragma unroll
                for (int r = 0; r < 3; r++) {
                    const int iy = oy + r - 1;
                    if (iy < 0 || iy > 31) continue;
#pragma unroll
                    for (int s = 0; s < 3; s++) {
                        const int ix = ox + s - 1;
                        if (ix < 0 || ix > 31) continue;
                        sum += xs[ci * 1024 + iy * 32 + ix] * ws[ci * 9 + r * 3 + s];
                    }
                }
            }
            sum = fmaxf(sum, 0.0f);
            m = fmaxf(m, sum);
        }
    }
    out[(((long long)n * 64 + oc) * 16 + py) * 16 + px] = m;
}

// ---------------------------------------------------------------------------
// im2col: col[k*N + n], k = ci*R*R + r*R + s, n = img*OH*OW + oy*OW + ox
// ---------------------------------------------------------------------------
__global__ __launch_bounds__(256) void im2col_kernel(
    const float* __restrict__ in, float* __restrict__ col,
    int C, int H, int W, int R, int pad, int OH, int OW, int N, long long total) {
    long long idx = (long long)blockIdx.x * 256 + threadIdx.x;
    if (idx >= total) return;
    const int n = (int)(idx % N);
    const int k = (int)(idx / N);
    const int s = k % R;
    const int r = (k / R) % R;
    const int ci = k / (R * R);
    const int ox = n % OW;
    const int oy = (n / OW) % OH;
    const int img = n / (OW * OH);
    const int iy = oy + r - pad;
    const int ix = ox + s - pad;
    float v = 0.0f;
    if (iy >= 0 && iy < H && ix >= 0 && ix < W)
        v = in[(((long long)img * C + ci) * H + iy) * W + ix];
    col[idx] = v;
}

// ---------------------------------------------------------------------------
// maxpool 2x2 stride 2
// ---------------------------------------------------------------------------
__global__ __launch_bounds__(256) void maxpool_kernel(
    const float* __restrict__ in, float* __restrict__ out,
    int C, int H, int W, long long total) {
    long long idx = (long long)blockIdx.x * 256 + threadIdx.x;
    if (idx >= total) return;
    const int OW = W >> 1, OH = H >> 1;
    const int x = (int)(idx % OW);
    const int y = (int)((idx / OW) % OH);
    const long long nc = idx / ((long long)OW * OH);  // n*C + c combined
    const float* p = in + (nc * H + 2 * y) * W + 2 * x;
    out[idx] = fmaxf(fmaxf(p[0], p[1]), fmaxf(p[W], p[W + 1]));
}

// ---------------------------------------------------------------------------
// SGEMM 128x128x16 for convs: C[M,N] = A[M,K] * Bc[K,N] ; A=weights row-major,
// Bc=im2col. Epilogue: +bias, relu, write NCHW: out[((n/HW)*M + m)*HW + n%HW]
// Requires: K % 16 == 0, N % 128 == 0 (true for all conv calls).
// ---------------------------------------------------------------------------
__global__ __launch_bounds__(256) void gemm128_conv(
    const float* __restrict__ A, const float* __restrict__ Bc,
    const float* __restrict__ bias, float* __restrict__ out,
    int M, int N, int K, int HW, int relu) {
    __shared__ float As[16][128];
    __shared__ float Bs[16][128];
    const int tid = threadIdx.x;
    const int m0 = blockIdx.y * 128;
    const int n0 = blockIdx.x * 128;
    const int tx = tid & 15, ty = tid >> 4;

    float acc[8][8];
#pragma unroll
    for (int i = 0; i < 8; i++)
#pragma unroll
        for (int j = 0; j < 8; j++) acc[i][j] = 0.0f;

    for (int k0 = 0; k0 < K; k0 += 16) {
        // Load A tile 128x16 (512 float4, 2 per thread), store transposed
#pragma unroll
        for (int r = 0; r < 2; r++) {
            const int s = tid + r * 256;
            const int row = s >> 2, kq = s & 3;
            float4 v = make_float4(0.f, 0.f, 0.f, 0.f);
            if (m0 + row < M)
                v = *reinterpret_cast<const float4*>(
                    &A[(long long)(m0 + row) * K + k0 + kq * 4]);
            As[kq * 4 + 0][row] = v.x;
            As[kq * 4 + 1][row] = v.y;
            As[kq * 4 + 2][row] = v.z;
            As[kq * 4 + 3][row] = v.w;
        }
        // Load B tile 16x128 (512 float4, 2 per thread)
#pragma unroll
        for (int r = 0; r < 2; r++) {
            const int s = tid + r * 256;
            const int k = s >> 5, nq = s & 31;
            float4 v = *reinterpret_cast<const float4*>(
                &Bc[(long long)(k0 + k) * N + n0 + nq * 4]);
            *reinterpret_cast<float4*>(&Bs[k][nq * 4]) = v;
        }
        __syncthreads();
#pragma unroll
        for (int kk = 0; kk < 16; kk++) {
            float4 a0 = *reinterpret_cast<const float4*>(&As[kk][ty * 8]);
            float4 a1 = *reinterpret_cast<const float4*>(&As[kk][ty * 8 + 4]);
            float4 b0 = *reinterpret_cast<const float4*>(&Bs[kk][tx * 8]);
            float4 b1 = *reinterpret_cast<const float4*>(&Bs[kk][tx * 8 + 4]);
            float a[8] = {a0.x, a0.y, a0.z, a0.w, a1.x, a1.y, a1.z, a1.w};
            float bb[8] = {b0.x, b0.y, b0.z, b0.w, b1.x, b1.y, b1.z, b1.w};
#pragma unroll
            for (int i = 0; i < 8; i++)
#pragma unroll
                for (int j = 0; j < 8; j++) acc[i][j] += a[i] * bb[j];
        }
        __syncthreads();
    }

#pragma unroll
    for (int i = 0; i < 8; i++) {
        const int m = m0 + ty * 8 + i;
        if (m >= M) continue;
        const float bv = bias[m];
#pragma unroll
        for (int j = 0; j < 8; j++) {
            const int n = n0 + tx * 8 + j;
            float v = acc[i][j] + bv;
            if (relu) v = fmaxf(v, 0.0f);
            const int img = n / HW, hw = n % HW;
            out[((long long)img * M + m) * HW + hw] = v;
        }
    }
}

// ---------------------------------------------------------------------------
// SGEMM 64x64x16 for FC: out[n, m] = sum_k W[m,k]*Act[n,k] + bias[m]
// Requires K % 16 == 0, N % 64 == 0 (N=256). M may be ragged (fc3: 1000).
// ---------------------------------------------------------------------------
__global__ __launch_bounds__(256) void gemm64_fc(
    const float* __restrict__ A, const float* __restrict__ Act,
    const float* __restrict__ bias, float* __restrict__ out,
    int M, int N, int K, int relu) {
    __shared__ float As[16][64];
    __shared__ float Bs[16][64];
    const int tid = threadIdx.x;
    const int m0 = blockIdx.y * 64;
    const int n0 = blockIdx.x * 64;
    const int tx = tid & 15, ty = tid >> 4;

    float acc[4][4];
#pragma unroll
    for (int i = 0; i < 4; i++)
#pragma unroll
        for (int j = 0; j < 4; j++) acc[i][j] = 0.0f;

    for (int k0 = 0; k0 < K; k0 += 16) {
        {
            const int row = tid >> 2, kq = tid & 3;
            float4 v = make_float4(0.f, 0.f, 0.f, 0.f);
            if (m0 + row < M)
                v = *reinterpret_cast<const float4*>(
                    &A[(long long)(m0 + row) * K + k0 + kq * 4]);
            As[kq * 4 + 0][row] = v.x;
            As[kq * 4 + 1][row] = v.y;
            As[kq * 4 + 2][row] = v.z;
            As[kq * 4 + 3][row] = v.w;
        }
        {
            const int ncol = tid >> 2, kq = tid & 3;
            float4 v = *reinterpret_cast<const float4*>(
                &Act[(long long)(n0 + ncol) * K + k0 + kq * 4]);
            Bs[kq * 4 + 0][ncol] = v.x;
            Bs[kq * 4 + 1][ncol] = v.y;
            Bs[kq * 4 + 2][ncol] = v.z;
            Bs[kq * 4 + 3][ncol] = v.w;
        }
        __syncthreads();
#pragma unroll
        for (int kk = 0; kk < 16; kk++) {
            float4 av = *reinterpret_cast<const float4*>(&As[kk][ty * 4]);
            float4 bv = *reinterpret_cast<const float4*>(&Bs[kk][tx * 4]);
            float a[4] = {av.x, av.y, av.z, av.w};
            float bb[4] = {bv.x, bv.y, bv.z, bv.w};
#pragma unroll
            for (int i = 0; i < 4; i++)
#pragma unroll
                for (int j = 0; j < 4; j++) acc[i][j] += a[i] * bb[j];
        }
        __syncthreads();
    }

#pragma unroll
    for (int i = 0; i < 4; i++) {
        const int m = m0 + ty * 4 + i;
        if (m >= M) continue;
        const float bv = bias[m];
#pragma unroll
        for (int j = 0; j < 4; j++) {
            const int n = n0 + tx * 4 + j;
            if (n >= N) continue;
            float v = acc[i][j] + bv;
            if (relu) v = fmaxf(v, 0.0f);
            out[(long long)n * M + m] = v;
        }
    }
}

// ---------------------------------------------------------------------------
// Host launcher
// ---------------------------------------------------------------------------
extern "C" void kernel_launch(void* const* d_in, const int* in_sizes, int n_in,
                              void* d_out, int out_size) {
    const float* x  = (const float*)d_in[0];
    const float* w1 = (const float*)d_in[1];
    const float* b1 = (const float*)d_in[2];
    const float* w2 = (const float*)d_in[3];
    const float* b2 = (const float*)d_in[4];
    const float* w3 = (const float*)d_in[5];
    const float* b3 = (const float*)d_in[6];
    const float* w4 = (const float*)d_in[7];
    const float* b4 = (const float*)d_in[8];
    const float* w5 = (const float*)d_in[9];
    const float* b5 = (const float*)d_in[10];
    const float* fw1 = (const float*)d_in[11];
    const float* fb1 = (const float*)d_in[12];
    const float* fw2 = (const float*)d_in[13];
    const float* fb2 = (const float*)d_in[14];
    const float* fw3 = (const float*)d_in[15];
    const float* fb3 = (const float*)d_in[16];
    float* out = (float*)d_out;

    float *act0, *act1, *col;
    cudaGetSymbolAddress((void**)&act0, g_act0);
    cudaGetSymbolAddress((void**)&act1, g_act1);
    cudaGetSymbolAddress((void**)&col, g_col);

    // conv1 + relu + pool -> act0 [256,64,16,16]
    conv1_pool_kernel<<<dim3(64, NIMG), 256>>>(x, w1, b1, act0);

    // conv2: 5x5 pad2, C=64, 16x16 -> 16x16
    {
        const int K = 64 * 25, N = NIMG * 16 * 16;  // 1600, 65536
        const long long total = (long long)K * N;
        im2col_kernel<<<(unsigned)((total + 255) / 256), 256>>>(
            act0, col, 64, 16, 16, 5, 2, 16, 16, N, total);
        gemm128_conv<<<dim3(N / 128, 2), 256>>>(w2, col, b2, act1, 192, N, K, 256, 1);
        // pool [256,192,16,16] -> act0 [256,192,8,8]
        const long long pt = (long long)NIMG * 192 * 8 * 8;
        maxpool_kernel<<<(unsigned)((pt + 255) / 256), 256>>>(act1, act0, 192, 16, 16, pt);
    }
    // conv3: 3x3 pad1, C=192, 8x8
    {
        const int K = 192 * 9, N = NIMG * 64;  // 1728, 16384
        const long long total = (long long)K * N;
        im2col_kernel<<<(unsigned)((total + 255) / 256), 256>>>(
            act0, col, 192, 8, 8, 3, 1, 8, 8, N, total);
        gemm128_conv<<<dim3(N / 128, 3), 256>>>(w3, col, b3, act1, 384, N, K, 64, 1);
    }
    // conv4: 3x3 pad1, C=384
    {
        const int K = 384 * 9, N = NIMG * 64;  // 3456
        const long long total = (long long)K * N;
        im2col_kernel<<<(unsigned)((total + 255) / 256), 256>>>(
            act1, col, 384, 8, 8, 3, 1, 8, 8, N, total);
        gemm128_conv<<<dim3(N / 128, 2), 256>>>(w4, col, b4, act0, 256, N, K, 64, 1);
    }
    // conv5: 3x3 pad1, C=256, then pool to 4x4
    {
        const int K = 256 * 9, N = NIMG * 64;  // 2304
        const long long total = (long long)K * N;
        im2col_kernel<<<(unsigned)((total + 255) / 256), 256>>>(
            act0, col, 256, 8, 8, 3, 1, 8, 8, N, total);
        gemm128_conv<<<dim3(N / 128, 2), 256>>>(w5, col, b5, act1, 256, N, K, 64, 1);
        const long long pt = (long long)NIMG * 256 * 4 * 4;
        maxpool_kernel<<<(unsigned)((pt + 255) / 256), 256>>>(act1, act0, 256, 8, 8, pt);
    }
    // fc1: [256,4096] @ fw1^T -> act1 [256,4096], relu
    gemm64_fc<<<dim3(4, 64), 256>>>(fw1, act0, fb1, act1, 4096, NIMG, 4096, 1);
    // fc2 -> act0
    gemm64_fc<<<dim3(4, 64), 256>>>(fw2, act1, fb2, act0, 4096, NIMG, 4096, 1);
    // fc3 -> d_out [256,1000], no relu
    gemm64_fc<<<dim3(4, 16), 256>>>(fw3, act0, fb3, out, 1000, NIMG, 4096, 0);
}

// round 2
// speedup vs baseline: 1.1473x; 1.1473x over previous
#include <cuda_runtime.h>
#include <cstdint>

// ---------------------------------------------------------------------------
// AlexNet (CIFAR) forward, B=256, fp32 I/O.
// conv1 fused (conv+relu+pool) -> [im2col + TF32x3 tensor-core GEMM] x4
// -> maxpools -> TF32x3 FC GEMMs.
// ---------------------------------------------------------------------------

#define NIMG 256

__device__ float g_act0[NIMG * 192 * 16 * 16];
__device__ float g_act1[NIMG * 192 * 16 * 16];
__device__ float g_col[1600 * 65536];

// ---------------- tf32 helpers ----------------
__device__ __forceinline__ uint32_t f2tf32(float v) {
    uint32_t u;
    asm("cvt.rna.tf32.f32 %0, %1;" : "=r"(u) : "f"(v));
    return u;
}
__device__ __forceinline__ void split_tf32(float v, float& hi, float& lo) {
    uint32_t u = f2tf32(v);
    hi = __uint_as_float(u);
    float rem = v - hi;
    lo = __uint_as_float(f2tf32(rem));
}
__device__ __forceinline__ void mma_tf32(float* d, const uint32_t* a, const uint32_t* b) {
    asm volatile(
        "mma.sync.aligned.m16n8k8.row.col.f32.tf32.tf32.f32 "
        "{%0,%1,%2,%3}, {%4,%5,%6,%7}, {%8,%9}, {%0,%1,%2,%3};"
        : "+f"(d[0]), "+f"(d[1]), "+f"(d[2]), "+f"(d[3])
        : "r"(a[0]), "r"(a[1]), "r"(a[2]), "r"(a[3]), "r"(b[0]), "r"(b[1]));
}

// ---------------------------------------------------------------------------
// conv1: 3x3 C3 pad1 32x32 -> relu -> maxpool2 -> [256,64,16,16]
// ---------------------------------------------------------------------------
__global__ __launch_bounds__(256) void conv1_pool_kernel(
    const float* __restrict__ x, const float* __restrict__ w,
    const float* __restrict__ b, float* __restrict__ out) {
    __shared__ float xs[3 * 32 * 32];
    __shared__ float ws[27];
    const int oc = blockIdx.x;
    const int n = blockIdx.y;
    const int tid = threadIdx.x;

    const float* xn = x + (long long)n * 3 * 32 * 32;
    for (int i = tid; i < 3 * 32 * 32; i += 256) xs[i] = xn[i];
    if (tid < 27) ws[tid] = w[oc * 27 + tid];
    __syncthreads();

    const float bias = b[oc];
    const int px = tid & 15, py = tid >> 4;
    float m = -1e30f;
#pragma unroll
    for (int dy = 0; dy < 2; dy++) {
#pragma unroll
        for (int dx = 0; dx < 2; dx++) {
            const int oy = 2 * py + dy, ox = 2 * px + dx;
            float sum = bias;
#pragma unroll
            for (int ci = 0; ci < 3; ci++) {
#pragma unroll
                for (int r = 0; r < 3; r++) {
                    const int iy = oy + r - 1;
                    if (iy < 0 || iy > 31) continue;
#pragma unroll
                    for (int s = 0; s < 3; s++) {
                        const int ix = ox + s - 1;
                        if (ix < 0 || ix > 31) continue;
                        sum += xs[ci * 1024 + iy * 32 + ix] * ws[ci * 9 + r * 3 + s];
                    }
                }
            }
            sum = fmaxf(sum, 0.0f);
            m = fmaxf(m, sum);
        }
    }
    out[(((long long)n * 64 + oc) * 16 + py) * 16 + px] = m;
}

// ---------------------------------------------------------------------------
// im2col: col[k*N + n]
// ---------------------------------------------------------------------------
__global__ __launch_bounds__(256) void im2col_kernel(
    const float* __restrict__ in, float* __restrict__ col,
    int C, int H, int W, int R, int pad, int OH, int OW, int N, long long total) {
    long long idx = (long long)blockIdx.x * 256 + threadIdx.x;
    if (idx >= total) return;
    const int n = (int)(idx % N);
    const int k = (int)(idx / N);
    const int s = k % R;
    const int r = (k / R) % R;
    const int ci = k / (R * R);
    const int ox = n % OW;
    const int oy = (n / OW) % OH;
    const int img = n / (OW * OH);
    const int iy = oy + r - pad;
    const int ix = ox + s - pad;
    float v = 0.0f;
    if (iy >= 0 && iy < H && ix >= 0 && ix < W)
        v = in[(((long long)img * C + ci) * H + iy) * W + ix];
    col[idx] = v;
}

// ---------------------------------------------------------------------------
// maxpool 2x2 stride 2
// ---------------------------------------------------------------------------
__global__ __launch_bounds__(256) void maxpool_kernel(
    const float* __restrict__ in, float* __restrict__ out,
    int C, int H, int W, long long total) {
    long long idx = (long long)blockIdx.x * 256 + threadIdx.x;
    if (idx >= total) return;
    const int OW = W >> 1, OH = H >> 1;
    const int x = (int)(idx % OW);
    const int y = (int)((idx / OW) % OH);
    const long long nc = idx / ((long long)OW * OH);
    const float* p = in + (nc * H + 2 * y) * W + 2 * x;
    out[idx] = fmaxf(fmaxf(p[0], p[1]), fmaxf(p[W], p[W + 1]));
}

// ---------------------------------------------------------------------------
// TF32x3 tensor-core GEMM.
//   C[M,N] = A[M,K] @ B ; A = weights [M,K] row-major.
//   MODE 0 (conv): B = col [K,N] row-major; epilogue writes NCHW.
//   MODE 1 (FC):   B = Act [N,K] row-major (transposed on load); out[n*M+m].
// Block: BM x 128, K-step 16. 8 warps; warp tile (BM/2) x 32 of m16n8k8.
// Requires: K%16==0, N%128==0. M may be ragged.
// ---------------------------------------------------------------------------
template <int BM, int MODE>
__global__ __launch_bounds__(256) void gemm_tf32(
    const float* __restrict__ A, const float* __restrict__ B,
    const float* __restrict__ bias, float* __restrict__ out,
    int M, int N, int K, int HW, int relu) {
    constexpr int BN = 128, BK = 16, PAD = 8;
    constexpr int WTM = BM / 2;       // 64 or 32
    constexpr int TM = WTM / 16;      // 4 or 2
    constexpr int TN = 4;
    constexpr int LB = (BM == 128) ? 7 : 6;

    __shared__ float Ah[BK][BM + PAD];
    __shared__ float Al[BK][BM + PAD];
    __shared__ float Bh[BK][BN + PAD];
    __shared__ float Bl[BK][BN + PAD];

    const int tid = threadIdx.x;
    const int lane = tid & 31, warp = tid >> 5;
    const int g = lane >> 2, tg = lane & 3;
    const int warp_m = (warp >> 2) * WTM;
    const int warp_n = (warp & 3) * 32;
    const int m0 = blockIdx.y * BM, n0 = blockIdx.x * BN;

    float acc[TM][TN][4];
#pragma unroll
    for (int i = 0; i < TM; i++)
#pragma unroll
        for (int j = 0; j < TN; j++)
#pragma unroll
            for (int e = 0; e < 4; e++) acc[i][j][e] = 0.0f;

    for (int k0 = 0; k0 < K; k0 += BK) {
        // ---- load A tile (BM x 16), transposed scatter with hi/lo split ----
#pragma unroll
        for (int r = 0; r < (BM * 4) / 256; r++) {
            const int c = tid + r * 256;
            const int m = c & (BM - 1);
            const int kg = c >> LB;  // 0..3
            const int k = kg * 4;
            float4 v = make_float4(0.f, 0.f, 0.f, 0.f);
            if (m0 + m < M)
                v = *reinterpret_cast<const float4*>(&A[(long long)(m0 + m) * K + k0 + k]);
            float h, l;
            split_tf32(v.x, h, l); Ah[k + 0][m] = h; Al[k + 0][m] = l;
            split_tf32(v.y, h, l); Ah[k + 1][m] = h; Al[k + 1][m] = l;
            split_tf32(v.z, h, l); Ah[k + 2][m] = h; Al[k + 2][m] = l;
            split_tf32(v.w, h, l); Ah[k + 3][m] = h; Al[k + 3][m] = l;
        }
        // ---- load B tile (16 x 128) ----
        if (MODE == 0) {
#pragma unroll
            for (int r = 0; r < 2; r++) {
                const int c = tid + r * 256;
                const int n4 = c & 31;
                const int k = c >> 5;
                float4 v = *reinterpret_cast<const float4*>(
                    &B[(long long)(k0 + k) * N + n0 + n4 * 4]);
                float4 hi4, lo4;
                split_tf32(v.x, hi4.x, lo4.x);
                split_tf32(v.y, hi4.y, lo4.y);
                split_tf32(v.z, hi4.z, lo4.z);
                split_tf32(v.w, hi4.w, lo4.w);
                *reinterpret_cast<float4*>(&Bh[k][n4 * 4]) = hi4;
                *reinterpret_cast<float4*>(&Bl[k][n4 * 4]) = lo4;
            }
        } else {
#pragma unroll
            for (int r = 0; r < 2; r++) {
                const int c = tid + r * 256;
                const int n = c & 127;
                const int kg = c >> 7;  // 0..3
                const int k = kg * 4;
                float4 v = *reinterpret_cast<const float4*>(
                    &B[(long long)(n0 + n) * K + k0 + k]);
                float h, l;
                split_tf32(v.x, h, l); Bh[k + 0][n] = h; Bl[k + 0][n] = l;
                split_tf32(v.y, h, l); Bh[k + 1][n] = h; Bl[k + 1][n] = l;
                split_tf32(v.z, h, l); Bh[k + 2][n] = h; Bl[k + 2][n] = l;
                split_tf32(v.w, h, l); Bh[k + 3][n] = h; Bl[k + 3][n] = l;
            }
        }
        __syncthreads();

        // ---- compute: two k8 steps ----
#pragma unroll
        for (int ks = 0; ks < BK; ks += 8) {
            uint32_t ahf[TM][4], alf[TM][4], bhf[TN][2], blf[TN][2];
#pragma unroll
            for (int mi = 0; mi < TM; mi++) {
                const int mr = warp_m + mi * 16;
                ahf[mi][0] = __float_as_uint(Ah[ks + tg][mr + g]);
                ahf[mi][1] = __float_as_uint(Ah[ks + tg][mr + g + 8]);
                ahf[mi][2] = __float_as_uint(Ah[ks + tg + 4][mr + g]);
                ahf[mi][3] = __float_as_uint(Ah[ks + tg + 4][mr + g + 8]);
                alf[mi][0] = __float_as_uint(Al[ks + tg][mr + g]);
                alf[mi][1] = __float_as_uint(Al[ks + tg][mr + g + 8]);
                alf[mi][2] = __float_as_uint(Al[ks + tg + 4][mr + g]);
                alf[mi][3] = __float_as_uint(Al[ks + tg + 4][mr + g + 8]);
            }
#pragma unroll
            for (int ni = 0; ni < TN; ni++) {
                const int nc = warp_n + ni * 8;
                bhf[ni][0] = __float_as_uint(Bh[ks + tg][nc + g]);
                bhf[ni][1] = __float_as_uint(Bh[ks + tg + 4][nc + g]);
                blf[ni][0] = __float_as_uint(Bl[ks + tg][nc + g]);
                blf[ni][1] = __float_as_uint(Bl[ks + tg + 4][nc + g]);
            }
#pragma unroll
            for (int mi = 0; mi < TM; mi++)
#pragma unroll
                for (int ni = 0; ni < TN; ni++) {
                    mma_tf32(acc[mi][ni], ahf[mi], bhf[ni]);
                    mma_tf32(acc[mi][ni], alf[mi], bhf[ni]);
                    mma_tf32(acc[mi][ni], ahf[mi], blf[ni]);
                }
        }
        __syncthreads();
    }

    // ---- epilogue: bias + relu + store ----
#pragma unroll
    for (int mi = 0; mi < TM; mi++) {
#pragma unroll
        for (int ei = 0; ei < 2; ei++) {
            const int m = m0 + warp_m + mi * 16 + g + ei * 8;
            if (m >= M) continue;
            const float bv = bias[m];
#pragma unroll
            for (int ni = 0; ni < TN; ni++) {
#pragma unroll
                for (int ej = 0; ej < 2; ej++) {
                    const int n = n0 + warp_n + ni * 8 + 2 * tg + ej;
                    float v = acc[mi][ni][ei * 2 + ej] + bv;
                    if (relu) v = fmaxf(v, 0.0f);
                    if (MODE == 0) {
                        const int img = n / HW, hw = n - img * HW;
                        out[((long long)img * M + m) * HW + hw] = v;
                    } else {
                        out[(long long)n * M + m] = v;
                    }
                }
            }
        }
    }
}

// ---------------------------------------------------------------------------
// Host launcher
// ---------------------------------------------------------------------------
extern "C" void kernel_launch(void* const* d_in, const int* in_sizes, int n_in,
                              void* d_out, int out_size) {
    const float* x  = (const float*)d_in[0];
    const float* w1 = (const float*)d_in[1];
    const float* b1 = (const float*)d_in[2];
    const float* w2 = (const float*)d_in[3];
    const float* b2 = (const float*)d_in[4];
    const float* w3 = (const float*)d_in[5];
    const float* b3 = (const float*)d_in[6];
    const float* w4 = (const float*)d_in[7];
    const float* b4 = (const float*)d_in[8];
    const float* w5 = (const float*)d_in[9];
    const float* b5 = (const float*)d_in[10];
    const float* fw1 = (const float*)d_in[11];
    const float* fb1 = (const float*)d_in[12];
    const float* fw2 = (const float*)d_in[13];
    const float* fb2 = (const float*)d_in[14];
    const float* fw3 = (const float*)d_in[15];
    const float* fb3 = (const float*)d_in[16];
    float* out = (float*)d_out;

    float *act0, *act1, *col;
    cudaGetSymbolAddress((void**)&act0, g_act0);
    cudaGetSymbolAddress((void**)&act1, g_act1);
    cudaGetSymbolAddress((void**)&col, g_col);

    // conv1 + relu + pool -> act0 [256,64,16,16]
    conv1_pool_kernel<<<dim3(64, NIMG), 256>>>(x, w1, b1, act0);

    // conv2: 5x5 pad2, C=64, 16x16 -> [256,192,16,16] -> pool -> act0
    {
        const int K = 1600, N = NIMG * 256;  // 65536
        const long long total = (long long)K * N;
        im2col_kernel<<<(unsigned)((total + 255) / 256), 256>>>(
            act0, col, 64, 16, 16, 5, 2, 16, 16, N, total);
        gemm_tf32<64, 0><<<dim3(N / 128, 3), 256>>>(w2, col, b2, act1, 192, N, K, 256, 1);
        const long long pt = (long long)NIMG * 192 * 8 * 8;
        maxpool_kernel<<<(unsigned)((pt + 255) / 256), 256>>>(act1, act0, 192, 16, 16, pt);
    }
    // conv3: 3x3 pad1, C=192 -> [256,384,8,8] in act1
    {
        const int K = 1728, N = NIMG * 64;  // 16384
        const long long total = (long long)K * N;
        im2col_kernel<<<(unsigned)((total + 255) / 256), 256>>>(
            act0, col, 192, 8, 8, 3, 1, 8, 8, N, total);
        gemm_tf32<128, 0><<<dim3(N / 128, 3), 256>>>(w3, col, b3, act1, 384, N, K, 64, 1);
    }
    // conv4: 3x3 pad1, C=384 -> [256,256,8,8] in act0
    {
        const int K = 3456, N = NIMG * 64;
        const long long total = (long long)K * N;
        im2col_kernel<<<(unsigned)((total + 255) / 256), 256>>>(
            act1, col, 384, 8, 8, 3, 1, 8, 8, N, total);
        gemm_tf32<128, 0><<<dim3(N / 128, 2), 256>>>(w4, col, b4, act0, 256, N, K, 64, 1);
    }
    // conv5: 3x3 pad1, C=256 -> pool -> act0 [256,256,4,4]
    {
        const int K = 2304, N = NIMG * 64;
        const long long total = (long long)K * N;
        im2col_kernel<<<(unsigned)((total + 255) / 256), 256>>>(
            act0, col, 256, 8, 8, 3, 1, 8, 8, N, total);
        gemm_tf32<128, 0><<<dim3(N / 128, 2), 256>>>(w5, col, b5, act1, 256, N, K, 64, 1);
        const long long pt = (long long)NIMG * 256 * 4 * 4;
        maxpool_kernel<<<(unsigned)((pt + 255) / 256), 256>>>(act1, act0, 256, 8, 8, pt);
    }
    // fc1: act0 [256,4096] -> act1 [256,4096]
    gemm_tf32<64, 1><<<dim3(2, 64), 256>>>(fw1, act0, fb1, act1, 4096, NIMG, 4096, 0, 1);
    // fc2 -> act0
    gemm_tf32<64, 1><<<dim3(2, 64), 256>>>(fw2, act1, fb2, act0, 4096, NIMG, 4096, 0, 1);
    // fc3 -> d_out [256,1000]
    gemm_tf32<64, 1><<<dim3(2, 16), 256>>>(fw3, act0, fb3, out, 1000, NIMG, 4096, 0, 0);
}

// round 3
// speedup vs baseline: 1.3261x; 1.1558x over previous
#include <cuda_runtime.h>
#include <cuda_bf16.h>
#include <cstdint>

// ---------------------------------------------------------------------------
// AlexNet (CIFAR) forward, B=256, fp32 I/O.
// conv1 fused -> [im2col(bf16 hi/lo planes) + bf16x3 mma.sync GEMM] x4
// -> maxpools -> bf16x3 FC GEMMs.
// ---------------------------------------------------------------------------

#define NIMG 256

__device__ float g_act0[NIMG * 192 * 16 * 16];
__device__ float g_act1[NIMG * 192 * 16 * 16];
__device__ __nv_bfloat16 g_colh[1600 * 65536];
__device__ __nv_bfloat16 g_coll[1600 * 65536];

// ---------------- helpers ----------------
__device__ __forceinline__ uint32_t smem_u32(const void* p) {
    return (uint32_t)__cvta_generic_to_shared(p);
}
__device__ __forceinline__ void cp16(void* dst, const void* src) {
    asm volatile("cp.async.cg.shared.global [%0], [%1], 16;\n"
                 :: "r"(smem_u32(dst)), "l"(src));
}
__device__ __forceinline__ void cp_commit() {
    asm volatile("cp.async.commit_group;\n");
}
template <int N>
__device__ __forceinline__ void cp_wait() {
    asm volatile("cp.async.wait_group %0;\n" :: "n"(N));
}
__device__ __forceinline__ void ldm_x4(uint32_t& r0, uint32_t& r1, uint32_t& r2,
                                       uint32_t& r3, uint32_t addr) {
    asm volatile("ldmatrix.sync.aligned.m8n8.x4.shared.b16 {%0,%1,%2,%3}, [%4];\n"
                 : "=r"(r0), "=r"(r1), "=r"(r2), "=r"(r3) : "r"(addr));
}
__device__ __forceinline__ void ldm_x2t(uint32_t& r0, uint32_t& r1, uint32_t addr) {
    asm volatile("ldmatrix.sync.aligned.m8n8.x2.trans.shared.b16 {%0,%1}, [%2];\n"
                 : "=r"(r0), "=r"(r1) : "r"(addr));
}
__device__ __forceinline__ void ldm_x2(uint32_t& r0, uint32_t& r1, uint32_t addr) {
    asm volatile("ldmatrix.sync.aligned.m8n8.x2.shared.b16 {%0,%1}, [%2];\n"
                 : "=r"(r0), "=r"(r1) : "r"(addr));
}
__device__ __forceinline__ void mma_bf16(float* d, const uint32_t* a, const uint32_t* b) {
    asm volatile(
        "mma.sync.aligned.m16n8k16.row.col.f32.bf16.bf16.f32 "
        "{%0,%1,%2,%3}, {%4,%5,%6,%7}, {%8,%9}, {%0,%1,%2,%3};\n"
        : "+f"(d[0]), "+f"(d[1]), "+f"(d[2]), "+f"(d[3])
        : "r"(a[0]), "r"(a[1]), "r"(a[2]), "r"(a[3]), "r"(b[0]), "r"(b[1]));
}
__device__ __forceinline__ void bsplit(float v, float& hi, float& lo) {
    hi = __bfloat162float(__float2bfloat16_rn(v));
    lo = v - hi;
}

// ---------------------------------------------------------------------------
// conv1: 3x3 C3 pad1 32x32 -> relu -> maxpool2 -> [256,64,16,16]
// ---------------------------------------------------------------------------
__global__ __launch_bounds__(256) void conv1_pool_kernel(
    const float* __restrict__ x, const float* __restrict__ w,
    const float* __restrict__ b, float* __restrict__ out) {
    __shared__ float xs[3 * 32 * 32];
    __shared__ float ws[27];
    const int oc = blockIdx.x;
    const int n = blockIdx.y;
    const int tid = threadIdx.x;

    const float* xn = x + (long long)n * 3 * 32 * 32;
    for (int i = tid; i < 3 * 32 * 32; i += 256) xs[i] = xn[i];
    if (tid < 27) ws[tid] = w[oc * 27 + tid];
    __syncthreads();

    const float bias = b[oc];
    const int px = tid & 15, py = tid >> 4;
    float m = -1e30f;
#pragma unroll
    for (int dy = 0; dy < 2; dy++) {
#pragma unroll
        for (int dx = 0; dx < 2; dx++) {
            const int oy = 2 * py + dy, ox = 2 * px + dx;
            float sum = bias;
#pragma unroll
            for (int ci = 0; ci < 3; ci++) {
#pragma unroll
                for (int r = 0; r < 3; r++) {
                    const int iy = oy + r - 1;
                    if (iy < 0 || iy > 31) continue;
#pragma unroll
                    for (int s = 0; s < 3; s++) {
                        const int ix = ox + s - 1;
                        if (ix < 0 || ix > 31) continue;
                        sum += xs[ci * 1024 + iy * 32 + ix] * ws[ci * 9 + r * 3 + s];
                    }
                }
            }
            sum = fmaxf(sum, 0.0f);
            m = fmaxf(m, sum);
        }
    }
    out[(((long long)n * 64 + oc) * 16 + py) * 16 + px] = m;
}

// ---------------------------------------------------------------------------
// im2col with bf16 hi/lo split: colh/coll[k*N + n]
// ---------------------------------------------------------------------------
__global__ __launch_bounds__(256) void im2col_split_kernel(
    const float* __restrict__ in, __nv_bfloat16* __restrict__ colh,
    __nv_bfloat16* __restrict__ coll,
    int C, int H, int W, int R, int pad, int OH, int OW, int N, long long total) {
    long long idx = (long long)blockIdx.x * 256 + threadIdx.x;
    if (idx >= total) return;
    const int n = (int)(idx % N);
    const int k = (int)(idx / N);
    const int s = k % R;
    const int r = (k / R) % R;
    const int ci = k / (R * R);
    const int ox = n % OW;
    const int oy = (n / OW) % OH;
    const int img = n / (OW * OH);
    const int iy = oy + r - pad;
    const int ix = ox + s - pad;
    float v = 0.0f;
    if (iy >= 0 && iy < H && ix >= 0 && ix < W)
        v = in[(((long long)img * C + ci) * H + iy) * W + ix];
    float hi, lo;
    bsplit(v, hi, lo);
    colh[idx] = __float2bfloat16_rn(hi);
    coll[idx] = __float2bfloat16_rn(lo);
}

// ---------------------------------------------------------------------------
// maxpool 2x2 stride 2
// ---------------------------------------------------------------------------
__global__ __launch_bounds__(256) void maxpool_kernel(
    const float* __restrict__ in, float* __restrict__ out,
    int H, int W, long long total) {
    long long idx = (long long)blockIdx.x * 256 + threadIdx.x;
    if (idx >= total) return;
    const int OW = W >> 1, OH = H >> 1;
    const int x = (int)(idx % OW);
    const int y = (int)((idx / OW) % OH);
    const long long nc = idx / ((long long)OW * OH);
    const float* p = in + (nc * H + 2 * y) * W + 2 * x;
    out[idx] = fmaxf(fmaxf(p[0], p[1]), fmaxf(p[W], p[W + 1]));
}

// ---------------------------------------------------------------------------
// bf16x3 tensor-core GEMM, 2-stage cp.async pipeline, ldmatrix fragments.
//   C[M,N] = A[M,K] @ B + bias
//   A: fp32 [M][K] (split to bf16 hi/lo in-kernel on smem store).
//   MODE 0 (conv): B = bf16 planes Bh/Bl [K][N]; epilogue -> NCHW fp32.
//   MODE 1 (fc):   B = fp32 Bf [N][K] (split in-kernel); epilogue -> out[n*M+m].
// Block BM x 128, BK=16, 8 warps; warp tile (BM/2) x 32 of m16n8k16.
// Requires K%16==0, N%128==0. M ragged OK.
// ---------------------------------------------------------------------------
template <int BM, int MODE>
__global__ __launch_bounds__(256, 1) void gemm_bf16x3(
    const float* __restrict__ A,
    const __nv_bfloat16* __restrict__ Bph, const __nv_bfloat16* __restrict__ Bpl,
    const float* __restrict__ Bf,
    const float* __restrict__ bias, float* __restrict__ out,
    int M, int N, int K, int HW, int relu) {
    constexpr int BN = 128, BK = 16;
    constexpr int AST = 24;                       // A smem row stride (bf16)
    constexpr int WTM = BM / 2, TM = WTM / 16, TN = 4;
    constexpr int BROWS = (MODE == 0) ? 16 : 128;
    constexpr int BST = (MODE == 0) ? 136 : 24;   // B smem row stride

    __shared__ __nv_bfloat16 Ash[2][2][BM][AST];
    __shared__ __nv_bfloat16 Bsh[2][2][BROWS][BST];

    const int tid = threadIdx.x, lane = tid & 31, warp = tid >> 5;
    const int g = lane >> 2, tg = lane & 3;
    const int warp_m = (warp >> 2) * WTM;
    const int warp_n = (warp & 3) * 32;
    const int m0 = blockIdx.y * BM, n0 = blockIdx.x * BN;
    const int KT = K / BK;

    float acc[TM][TN][4];
#pragma unroll
    for (int i = 0; i < TM; i++)
#pragma unroll
        for (int j = 0; j < TN; j++)
#pragma unroll
            for (int e = 0; e < 4; e++) acc[i][j][e] = 0.0f;

// ---- stage loaders (as macros over buf/kt) ----
#define LOAD_A(kt_, buf_)                                                       \
    {                                                                           \
        const int k0_ = (kt_)*BK;                                               \
        _Pragma("unroll") for (int r = 0; r < (BM * 4) / 256; r++) {            \
            const int c = tid + r * 256;                                        \
            const int m = c >> 2, kq = (c & 3) * 4;                             \
            float4 v = make_float4(0.f, 0.f, 0.f, 0.f);                         \
            if (m0 + m < M)                                                     \
                v = *reinterpret_cast<const float4*>(                           \
                    &A[(size_t)(m0 + m) * K + k0_ + kq]);                       \
            float h0, l0, h1, l1, h2, l2, h3, l3;                               \
            bsplit(v.x, h0, l0); bsplit(v.y, h1, l1);                           \
            bsplit(v.z, h2, l2); bsplit(v.w, h3, l3);                           \
            *reinterpret_cast<__nv_bfloat162*>(&Ash[buf_][0][m][kq]) =          \
                __floats2bfloat162_rn(h0, h1);                                  \
            *reinterpret_cast<__nv_bfloat162*>(&Ash[buf_][0][m][kq + 2]) =      \
                __floats2bfloat162_rn(h2, h3);                                  \
            *reinterpret_cast<__nv_bfloat162*>(&Ash[buf_][1][m][kq]) =          \
                __floats2bfloat162_rn(l0, l1);                                  \
            *reinterpret_cast<__nv_bfloat162*>(&Ash[buf_][1][m][kq + 2]) =      \
                __floats2bfloat162_rn(l2, l3);                                  \
        }                                                                       \
    }

#define LOAD_B_CONV(kt_, buf_)                                                  \
    {                                                                           \
        const int k0_ = (kt_)*BK;                                               \
        _Pragma("unroll") for (int r = 0; r < 2; r++) {                         \
            const int c = tid + r * 256;                                        \
            const int p = c >> 8, rem = c & 255;                                \
            const int k = rem >> 4, seg = rem & 15;                             \
            const __nv_bfloat16* src =                                          \
                (p ? Bpl : Bph) + (size_t)(k0_ + k) * N + n0 + seg * 8;         \
            cp16(&Bsh[buf_][p][k][seg * 8], src);                               \
        }                                                                       \
    }

#define LOAD_B_FC(kt_, buf_)                                                    \
    {                                                                           \
        const int k0_ = (kt_)*BK;                                               \
        _Pragma("unroll") for (int r = 0; r < 2; r++) {                         \
            const int c = tid + r * 256;                                        \
            const int n = c >> 2, kq = (c & 3) * 4;                             \
            float4 v = *reinterpret_cast<const float4*>(                        \
                &Bf[(size_t)(n0 + n) * K + k0_ + kq]);                          \
            float h0, l0, h1, l1, h2, l2, h3, l3;                               \
            bsplit(v.x, h0, l0); bsplit(v.y, h1, l1);                           \
            bsplit(v.z, h2, l2); bsplit(v.w, h3, l3);                           \
            *reinterpret_cast<__nv_bfloat162*>(&Bsh[buf_][0][n][kq]) =          \
                __floats2bfloat162_rn(h0, h1);                                  \
            *reinterpret_cast<__nv_bfloat162*>(&Bsh[buf_][0][n][kq + 2]) =      \
                __floats2bfloat162_rn(h2, h3);                                  \
            *reinterpret_cast<__nv_bfloat162*>(&Bsh[buf_][1][n][kq]) =          \
                __floats2bfloat162_rn(l0, l1);                                  \
            *reinterpret_cast<__nv_bfloat162*>(&Bsh[buf_][1][n][kq + 2]) =      \
                __floats2bfloat162_rn(l2, l3);                                  \
        }                                                                       \
    }

    // prologue: stage 0
    LOAD_A(0, 0);
    if (MODE == 0) { LOAD_B_CONV(0, 0); cp_commit(); }
    else { LOAD_B_FC(0, 0); }

    int buf = 0;
    for (int kt = 0; kt < KT; kt++) {
        if (kt + 1 < KT) {
            LOAD_A(kt + 1, buf ^ 1);
            if (MODE == 0) { LOAD_B_CONV(kt + 1, buf ^ 1); cp_commit(); cp_wait<1>(); }
            else { LOAD_B_FC(kt + 1, buf ^ 1); }
        } else {
            if (MODE == 0) cp_wait<0>();
        }
        __syncthreads();

        // ---- fragments + mma ----
        uint32_t bh[TN][2], bl[TN][2];
#pragma unroll
        for (int ni = 0; ni < TN; ni++) {
            if (MODE == 0) {
                const int krow = lane & 15;
                const int ncol = warp_n + ni * 8;
                ldm_x2t(bh[ni][0], bh[ni][1], smem_u32(&Bsh[buf][0][krow][ncol]));
                ldm_x2t(bl[ni][0], bl[ni][1], smem_u32(&Bsh[buf][1][krow][ncol]));
            } else {
                const int nrow = warp_n + ni * 8 + (lane & 7);
                const int kcol = ((lane >> 3) & 1) * 8;
                ldm_x2(bh[ni][0], bh[ni][1], smem_u32(&Bsh[buf][0][nrow][kcol]));
                ldm_x2(bl[ni][0], bl[ni][1], smem_u32(&Bsh[buf][1][nrow][kcol]));
            }
        }
#pragma unroll
        for (int mi = 0; mi < TM; mi++) {
            const int mrow = warp_m + mi * 16 + (lane & 15);
            const int kcol = (lane >> 4) * 8;
            uint32_t ah[4], al[4];
            ldm_x4(ah[0], ah[1], ah[2], ah[3], smem_u32(&Ash[buf][0][mrow][kcol]));
            ldm_x4(al[0], al[1], al[2], al[3], smem_u32(&Ash[buf][1][mrow][kcol]));
#pragma unroll
            for (int ni = 0; ni < TN; ni++) {
                mma_bf16(acc[mi][ni], ah, bh[ni]);
                mma_bf16(acc[mi][ni], al, bh[ni]);
                mma_bf16(acc[mi][ni], ah, bl[ni]);
            }
        }
        buf ^= 1;
        __syncthreads();
    }

    // ---- epilogue ----
#pragma unroll
    for (int mi = 0; mi < TM; mi++) {
#pragma unroll
        for (int ei = 0; ei < 2; ei++) {
            const int m = m0 + warp_m + mi * 16 + g + ei * 8;
            if (m >= M) continue;
            const float bv = bias[m];
#pragma unroll
            for (int ni = 0; ni < TN; ni++) {
#pragma unroll
                for (int ej = 0; ej < 2; ej++) {
                    const int n = n0 + warp_n + ni * 8 + 2 * tg + ej;
                    float v = acc[mi][ni][ei * 2 + ej] + bv;
                    if (relu) v = fmaxf(v, 0.0f);
                    if (MODE == 0) {
                        const int img = n / HW, hw = n - img * HW;
                        out[((size_t)img * M + m) * HW + hw] = v;
                    } else {
                        out[(size_t)n * M + m] = v;
                    }
                }
            }
        }
    }
#undef LOAD_A
#undef LOAD_B_CONV
#undef LOAD_B_FC
}

// ---------------------------------------------------------------------------
// Host launcher
// ---------------------------------------------------------------------------
extern "C" void kernel_launch(void* const* d_in, const int* in_sizes, int n_in,
                              void* d_out, int out_size) {
    const float* x  = (const float*)d_in[0];
    const float* w1 = (const float*)d_in[1];
    const float* b1 = (const float*)d_in[2];
    const float* w2 = (const float*)d_in[3];
    const float* b2 = (const float*)d_in[4];
    const float* w3 = (const float*)d_in[5];
    const float* b3 = (const float*)d_in[6];
    const float* w4 = (const float*)d_in[7];
    const float* b4 = (const float*)d_in[8];
    const float* w5 = (const float*)d_in[9];
    const float* b5 = (const float*)d_in[10];
    const float* fw1 = (const float*)d_in[11];
    const float* fb1 = (const float*)d_in[12];
    const float* fw2 = (const float*)d_in[13];
    const float* fb2 = (const float*)d_in[14];
    const float* fw3 = (const float*)d_in[15];
    const float* fb3 = (const float*)d_in[16];
    float* out = (float*)d_out;

    float *act0, *act1;
    __nv_bfloat16 *colh, *coll;
    cudaGetSymbolAddress((void**)&act0, g_act0);
    cudaGetSymbolAddress((void**)&act1, g_act1);
    cudaGetSymbolAddress((void**)&colh, g_colh);
    cudaGetSymbolAddress((void**)&coll, g_coll);

    // conv1 + relu + pool -> act0 [256,64,16,16]
    conv1_pool_kernel<<<dim3(64, NIMG), 256>>>(x, w1, b1, act0);

    // conv2: 5x5 pad2, C=64 -> [256,192,16,16] -> pool -> act0
    {
        const int K = 1600, N = NIMG * 256;
        const long long total = (long long)K * N;
        im2col_split_kernel<<<(unsigned)((total + 255) / 256), 256>>>(
            act0, colh, coll, 64, 16, 16, 5, 2, 16, 16, N, total);
        gemm_bf16x3<128, 0><<<dim3(N / 128, 2), 256>>>(
            w2, colh, coll, nullptr, b2, act1, 192, N, K, 256, 1);
        const long long pt = (long long)NIMG * 192 * 8 * 8;
        maxpool_kernel<<<(unsigned)((pt + 255) / 256), 256>>>(act1, act0, 16, 16, pt);
    }
    // conv3: 3x3 pad1, C=192 -> [256,384,8,8] in act1
    {
        const int K = 1728, N = NIMG * 64;
        const long long total = (long long)K * N;
        im2col_split_kernel<<<(unsigned)((total + 255) / 256), 256>>>(
            act0, colh, coll, 192, 8, 8, 3, 1, 8, 8, N, total);
        gemm_bf16x3<128, 0><<<dim3(N / 128, 3), 256>>>(
            w3, colh, coll, nullptr, b3, act1, 384, N, K, 64, 1);
    }
    // conv4: 3x3 pad1, C=384 -> [256,256,8,8] in act0
    {
        const int K = 3456, N = NIMG * 64;
        const long long total = (long long)K * N;
        im2col_split_kernel<<<(unsigned)((total + 255) / 256), 256>>>(
            act1, colh, coll, 384, 8, 8, 3, 1, 8, 8, N, total);
        gemm_bf16x3<128, 0><<<dim3(N / 128, 2), 256>>>(
            w4, colh, coll, nullptr, b4, act0, 256, N, K, 64, 1);
    }
    // conv5: 3x3 pad1, C=256 -> pool -> act0 [256,256,4,4] = [256][4096]
    {
        const int K = 2304, N = NIMG * 64;
        const long long total = (long long)K * N;
        im2col_split_kernel<<<(unsigned)((total + 255) / 256), 256>>>(
            act0, colh, coll, 256, 8, 8, 3, 1, 8, 8, N, total);
        gemm_bf16x3<128, 0><<<dim3(N / 128, 2), 256>>>(
            w5, colh, coll, nullptr, b5, act1, 256, N, K, 64, 1);
        const long long pt = (long long)NIMG * 256 * 4 * 4;
        maxpool_kernel<<<(unsigned)((pt + 255) / 256), 256>>>(act1, act0, 8, 8, pt);
    }
    // fc1: act0 [256][4096] -> act1 [256][4096], relu
    gemm_bf16x3<64, 1><<<dim3(2, 64), 256>>>(
        fw1, nullptr, nullptr, act0, fb1, act1, 4096, NIMG, 4096, 0, 1);
    // fc2 -> act0
    gemm_bf16x3<64, 1><<<dim3(2, 64), 256>>>(
        fw2, nullptr, nullptr, act1, fb2, act0, 4096, NIMG, 4096, 0, 1);
    // fc3 -> d_out [256,1000], no relu
    gemm_bf16x3<64, 1><<<dim3(2, 16), 256>>>(
        fw3, nullptr, nullptr, act0, fb3, out, 1000, NIMG, 4096, 0, 0);
}

// round 4
// speedup vs baseline: 1.7692x; 1.3342x over previous
#include <cuda_runtime.h>
#include <cuda_bf16.h>
#include <cstdint>

// ---------------------------------------------------------------------------
// AlexNet (CIFAR) forward, B=256, fp32 I/O.
// Weights pre-split to padded bf16 hi/lo planes. All GEMM operands are bf16
// planes; mainloop = cp.async + ldmatrix + mma.sync (bf16x3, 3 passes).
// ---------------------------------------------------------------------------

#define NIMG 256

__device__ float g_act0[NIMG * 192 * 16 * 16];
__device__ float g_act1[NIMG * 192 * 16 * 16];
__device__ __nv_bfloat16 g_colh[1600 * 65536];
__device__ __nv_bfloat16 g_coll[1600 * 65536];
__device__ __nv_bfloat16 g_wh[40296448];
__device__ __nv_bfloat16 g_wl[40296448];
__device__ __nv_bfloat16 g_fbh[3 * 4096 * 256];
__device__ __nv_bfloat16 g_fbl[3 * 4096 * 256];

// weight plane offsets (elements), Mpad x K each
#define OFF_W2  0            // 256 x 1600
#define OFF_W3  409600       // 384 x 1728
#define OFF_W4  1073152      // 256 x 3456
#define OFF_W5  1957888      // 256 x 2304
#define OFF_FW1 2547712      // 4096 x 4096
#define OFF_FW2 19324928     // 4096 x 4096
#define OFF_FW3 36102144     // 1024 x 4096

// ---------------- helpers ----------------
__device__ __forceinline__ uint32_t smem_u32(const void* p) {
    return (uint32_t)__cvta_generic_to_shared(p);
}
__device__ __forceinline__ void cp16(void* dst, const void* src) {
    asm volatile("cp.async.cg.shared.global [%0], [%1], 16;\n"
                 :: "r"(smem_u32(dst)), "l"(src));
}
__device__ __forceinline__ void cp_commit() {
    asm volatile("cp.async.commit_group;\n");
}
template <int N>
__device__ __forceinline__ void cp_wait() {
    asm volatile("cp.async.wait_group %0;\n" :: "n"(N));
}
__device__ __forceinline__ void ldm_x4(uint32_t& r0, uint32_t& r1, uint32_t& r2,
                                       uint32_t& r3, uint32_t addr) {
    asm volatile("ldmatrix.sync.aligned.m8n8.x4.shared.b16 {%0,%1,%2,%3}, [%4];\n"
                 : "=r"(r0), "=r"(r1), "=r"(r2), "=r"(r3) : "r"(addr));
}
__device__ __forceinline__ void ldm_x2t(uint32_t& r0, uint32_t& r1, uint32_t addr) {
    asm volatile("ldmatrix.sync.aligned.m8n8.x2.trans.shared.b16 {%0,%1}, [%2];\n"
                 : "=r"(r0), "=r"(r1) : "r"(addr));
}
__device__ __forceinline__ void mma_bf16(float* d, const uint32_t* a, const uint32_t* b) {
    asm volatile(
        "mma.sync.aligned.m16n8k16.row.col.f32.bf16.bf16.f32 "
        "{%0,%1,%2,%3}, {%4,%5,%6,%7}, {%8,%9}, {%0,%1,%2,%3};\n"
        : "+f"(d[0]), "+f"(d[1]), "+f"(d[2]), "+f"(d[3])
        : "r"(a[0]), "r"(a[1]), "r"(a[2]), "r"(a[3]), "r"(b[0]), "r"(b[1]));
}
__device__ __forceinline__ void bsplit(float v, float& hi, float& lo) {
    hi = __bfloat162float(__float2bfloat16_rn(v));
    lo = v - hi;
}

// ---------------------------------------------------------------------------
// weight split: fp32 [M][K] -> bf16 hi/lo planes [Mpad][K], zero padded rows
// ---------------------------------------------------------------------------
__global__ __launch_bounds__(256) void wsplit_kernel(
    const float* __restrict__ w, __nv_bfloat16* __restrict__ wh,
    __nv_bfloat16* __restrict__ wl, int M, int K, int total) {
    int idx = blockIdx.x * 256 + threadIdx.x;
    if (idx >= total) return;
    const int m = idx / K;
    float v = (m < M) ? w[idx] : 0.0f;
    float h, l;
    bsplit(v, h, l);
    wh[idx] = __float2bfloat16_rn(h);
    wl[idx] = __float2bfloat16_rn(l);
}

// ---------------------------------------------------------------------------
// transpose+split: fp32 [256][K] -> bf16 planes [K][256]
// ---------------------------------------------------------------------------
__global__ void tsplit_kernel(const float* __restrict__ in,
                              __nv_bfloat16* __restrict__ oh,
                              __nv_bfloat16* __restrict__ ol, int K) {
    __shared__ float t[32][33];
    const int k0 = blockIdx.x * 32, n0 = blockIdx.y * 32;
    t[threadIdx.y][threadIdx.x] =
        in[(size_t)(n0 + threadIdx.y) * K + k0 + threadIdx.x];
    __syncthreads();
    const int k = k0 + threadIdx.y, n = n0 + threadIdx.x;
    float h, l;
    bsplit(t[threadIdx.x][threadIdx.y], h, l);
    oh[(size_t)k * 256 + n] = __float2bfloat16_rn(h);
    ol[(size_t)k * 256 + n] = __float2bfloat16_rn(l);
}

// ---------------------------------------------------------------------------
// conv1: 3x3 C3 pad1 32x32 -> relu -> maxpool2 -> [256,64,16,16]
// ---------------------------------------------------------------------------
__global__ __launch_bounds__(256) void conv1_pool_kernel(
    const float* __restrict__ x, const float* __restrict__ w,
    const float* __restrict__ b, float* __restrict__ out) {
    __shared__ float xs[3 * 32 * 32];
    __shared__ float ws[27];
    const int oc = blockIdx.x;
    const int n = blockIdx.y;
    const int tid = threadIdx.x;

    const float* xn = x + (long long)n * 3 * 32 * 32;
    for (int i = tid; i < 3 * 32 * 32; i += 256) xs[i] = xn[i];
    if (tid < 27) ws[tid] = w[oc * 27 + tid];
    __syncthreads();

    const float bias = b[oc];
    const int px = tid & 15, py = tid >> 4;
    float m = -1e30f;
#pragma unroll
    for (int dy = 0; dy < 2; dy++) {
#pragma unroll
        for (int dx = 0; dx < 2; dx++) {
            const int oy = 2 * py + dy, ox = 2 * px + dx;
            float sum = bias;
#pragma unroll
            for (int ci = 0; ci < 3; ci++) {
#pragma unroll
                for (int r = 0; r < 3; r++) {
                    const int iy = oy + r - 1;
                    if (iy < 0 || iy > 31) continue;
#pragma unroll
                    for (int s = 0; s < 3; s++) {
                        const int ix = ox + s - 1;
                        if (ix < 0 || ix > 31) continue;
                        sum += xs[ci * 1024 + iy * 32 + ix] * ws[ci * 9 + r * 3 + s];
                    }
                }
            }
            sum = fmaxf(sum, 0.0f);
            m = fmaxf(m, sum);
        }
    }
    out[(((long long)n * 64 + oc) * 16 + py) * 16 + px] = m;
}

// ---------------------------------------------------------------------------
// im2col with bf16 hi/lo split: colh/coll[k*N + n]
// ---------------------------------------------------------------------------
__global__ __launch_bounds__(256) void im2col_split_kernel(
    const float* __restrict__ in, __nv_bfloat16* __restrict__ colh,
    __nv_bfloat16* __restrict__ coll,
    int C, int H, int W, int R, int pad, int OH, int OW, int N, long long total) {
    long long idx = (long long)blockIdx.x * 256 + threadIdx.x;
    if (idx >= total) return;
    const int n = (int)(idx % N);
    const int k = (int)(idx / N);
    const int s = k % R;
    const int r = (k / R) % R;
    const int ci = k / (R * R);
    const int ox = n % OW;
    const int oy = (n / OW) % OH;
    const int img = n / (OW * OH);
    const int iy = oy + r - pad;
    const int ix = ox + s - pad;
    float v = 0.0f;
    if (iy >= 0 && iy < H && ix >= 0 && ix < W)
        v = in[(((long long)img * C + ci) * H + iy) * W + ix];
    float hi, lo;
    bsplit(v, hi, lo);
    colh[idx] = __float2bfloat16_rn(hi);
    coll[idx] = __float2bfloat16_rn(lo);
}

// ---------------------------------------------------------------------------
// maxpool 2x2 stride 2
// ---------------------------------------------------------------------------
__global__ __launch_bounds__(256) void maxpool_kernel(
    const float* __restrict__ in, float* __restrict__ out,
    int H, int W, long long total) {
    long long idx = (long long)blockIdx.x * 256 + threadIdx.x;
    if (idx >= total) return;
    const int OW = W >> 1, OH = H >> 1;
    const int x = (int)(idx % OW);
    const int y = (int)((idx / OW) % OH);
    const long long nc = idx / ((long long)OW * OH);
    const float* p = in + (nc * H + 2 * y) * W + 2 * x;
    out[idx] = fmaxf(fmaxf(p[0], p[1]), fmaxf(p[W], p[W + 1]));
}

// ---------------------------------------------------------------------------
// bf16x3 tensor-core GEMM, all-bf16 operands, 2-stage cp.async pipeline.
//   C[M,N] = A[M,K] @ B[K,N] + bias
//   A: bf16 planes [Mpad][K] (pre-split, padded -> unguarded loads)
//   B: bf16 planes [K][N]
//   EPI 0: fp32 NCHW via HW. EPI 1: bf16 planes out[m*N+n] (+relu).
//   EPI 2: fp32 out[n*M+m].
// Block BM x 128, BK=32, 8 warps; warp tile (BM/2) x 32 of m16n8k16.
// Requires K%32==0, N%128==0, KT>=2.
// ---------------------------------------------------------------------------
template <int BM, int EPI>
__global__ __launch_bounds__(256, 2) void gemm_bf16x3(
    const __nv_bfloat16* __restrict__ Ah, const __nv_bfloat16* __restrict__ Al,
    const __nv_bfloat16* __restrict__ Bh, const __nv_bfloat16* __restrict__ Bl,
    const float* __restrict__ bias, float* __restrict__ outf,
    __nv_bfloat16* __restrict__ outh, __nv_bfloat16* __restrict__ outl,
    int M, int N, int K, int HW, int relu) {
    constexpr int AST = 40;    // A smem row stride (bf16): 32 data + 8 pad (80B)
    constexpr int BST = 136;   // B smem row stride: 128 data + 8 pad (272B)
    constexpr int WTM = BM / 2, TM = WTM / 16, TN = 4;
    constexpr int NA = BM / 32;          // A cp16s per thread
    constexpr int LA = (BM == 128) ? 9 : 8;

    extern __shared__ __align__(16) __nv_bfloat16 smem[];
    __nv_bfloat16* As = smem;                       // [2][2][BM][AST]
    __nv_bfloat16* Bs = smem + 2 * 2 * BM * AST;    // [2][2][32][BST]

    const int tid = threadIdx.x, lane = tid & 31, warp = tid >> 5;
    const int g = lane >> 2, tg = lane & 3;
    const int warp_m = (warp >> 2) * WTM;
    const int warp_n = (warp & 3) * 32;
    const int m0 = blockIdx.y * BM, n0 = blockIdx.x * 128;
    const int KT = K / 32;

#define AIDX(st, p, row, col) ((((st)*2 + (p)) * BM + (row)) * AST + (col))
#define BIDX(st, p, row, col) ((((st)*2 + (p)) * 32 + (row)) * BST + (col))

#define LOADT(kt_, st_)                                                        \
    {                                                                          \
        const int kbase = (kt_)*32;                                            \
        _Pragma("unroll") for (int i = 0; i < NA; i++) {                       \
            const int c = tid + i * 256;                                       \
            const int p = c >> LA, rem = c & ((1 << LA) - 1);                  \
            const int row = rem >> 2, ch = (rem & 3) * 8;                      \
            const __nv_bfloat16* s =                                           \
                (p ? Al : Ah) + (size_t)(m0 + row) * K + kbase + ch;           \
            cp16(&As[AIDX(st_, p, row, ch)], s);                               \
        }                                                                      \
        _Pragma("unroll") for (int i = 0; i < 4; i++) {                        \
            const int c = tid + i * 256;                                       \
            const int p = c >> 9, rem = c & 511;                               \
            const int row = rem >> 4, ch = (rem & 15) * 8;                     \
            const __nv_bfloat16* s =                                           \
                (p ? Bl : Bh) + (size_t)(kbase + row) * N + n0 + ch;           \
            cp16(&Bs[BIDX(st_, p, row, ch)], s);                               \
        }                                                                      \
    }

    float acc[TM][TN][4];
#pragma unroll
    for (int i = 0; i < TM; i++)
#pragma unroll
        for (int j = 0; j < TN; j++)
#pragma unroll
            for (int e = 0; e < 4; e++) acc[i][j][e] = 0.0f;

    LOADT(0, 0); cp_commit();
    LOADT(1, 1); cp_commit();

    for (int kt = 0; kt < KT; kt++) {
        if (kt == KT - 1) { cp_wait<0>(); } else { cp_wait<1>(); }
        __syncthreads();
        const int st = kt & 1;
#pragma unroll
        for (int ks = 0; ks < 32; ks += 16) {
            uint32_t bh[TN][2], bl[TN][2];
#pragma unroll
            for (int ni = 0; ni < TN; ni++) {
                const int krow = ks + (lane & 15);
                const int ncol = warp_n + ni * 8;
                ldm_x2t(bh[ni][0], bh[ni][1], smem_u32(&Bs[BIDX(st, 0, krow, ncol)]));
                ldm_x2t(bl[ni][0], bl[ni][1], smem_u32(&Bs[BIDX(st, 1, krow, ncol)]));
            }
#pragma unroll
            for (int mi = 0; mi < TM; mi++) {
                const int mrow = warp_m + mi * 16 + (lane & 15);
                const int kcol = ks + (lane >> 4) * 8;
                uint32_t ah[4], al[4];
                ldm_x4(ah[0], ah[1], ah[2], ah[3], smem_u32(&As[AIDX(st, 0, mrow, kcol)]));
                ldm_x4(al[0], al[1], al[2], al[3], smem_u32(&As[AIDX(st, 1, mrow, kcol)]));
#pragma unroll
                for (int ni = 0; ni < TN; ni++) {
                    mma_bf16(acc[mi][ni], ah, bh[ni]);
                    mma_bf16(acc[mi][ni], al, bh[ni]);
                    mma_bf16(acc[mi][ni], ah, bl[ni]);
                }
            }
        }
        __syncthreads();
        if (kt + 2 < KT) { LOADT(kt + 2, st); cp_commit(); }
    }

    // ---- epilogue ----
#pragma unroll
    for (int mi = 0; mi < TM; mi++) {
#pragma unroll
        for (int ei = 0; ei < 2; ei++) {
            const int m = m0 + warp_m + mi * 16 + g + ei * 8;
            if (m >= M) continue;
            const float bv = bias[m];
#pragma unroll
            for (int ni = 0; ni < TN; ni++) {
#pragma unroll
                for (int ej = 0; ej < 2; ej++) {
                    const int n = n0 + warp_n + ni * 8 + 2 * tg + ej;
                    float v = acc[mi][ni][ei * 2 + ej] + bv;
                    if (relu) v = fmaxf(v, 0.0f);
                    if (EPI == 0) {
                        const int img = n / HW, hw = n - img * HW;
                        outf[((size_t)img * M + m) * HW + hw] = v;
                    } else if (EPI == 1) {
                        float h, l;
                        bsplit(v, h, l);
                        outh[(size_t)m * N + n] = __float2bfloat16_rn(h);
                        outl[(size_t)m * N + n] = __float2bfloat16_rn(l);
                    } else {
                        outf[(size_t)n * M + m] = v;
                    }
                }
            }
        }
    }
#undef LOADT
#undef AIDX
#undef BIDX
}

// ---------------------------------------------------------------------------
// Host launcher
// ---------------------------------------------------------------------------
extern "C" void kernel_launch(void* const* d_in, const int* in_sizes, int n_in,
                              void* d_out, int out_size) {
    const float* x  = (const float*)d_in[0];
    const float* w1 = (const float*)d_in[1];
    const float* b1 = (const float*)d_in[2];
    const float* w2 = (const float*)d_in[3];
    const float* b2 = (const float*)d_in[4];
    const float* w3 = (const float*)d_in[5];
    const float* b3 = (const float*)d_in[6];
    const float* w4 = (const float*)d_in[7];
    const float* b4 = (const float*)d_in[8];
    const float* w5 = (const float*)d_in[9];
    const float* b5 = (const float*)d_in[10];
    const float* fw1 = (const float*)d_in[11];
    const float* fb1 = (const float*)d_in[12];
    const float* fw2 = (const float*)d_in[13];
    const float* fb2 = (const float*)d_in[14];
    const float* fw3 = (const float*)d_in[15];
    const float* fb3 = (const float*)d_in[16];
    float* out = (float*)d_out;

    float *act0, *act1;
    __nv_bfloat16 *colh, *coll, *wh, *wl, *fbh, *fbl;
    cudaGetSymbolAddress((void**)&act0, g_act0);
    cudaGetSymbolAddress((void**)&act1, g_act1);
    cudaGetSymbolAddress((void**)&colh, g_colh);
    cudaGetSymbolAddress((void**)&coll, g_coll);
    cudaGetSymbolAddress((void**)&wh, g_wh);
    cudaGetSymbolAddress((void**)&wl, g_wl);
    cudaGetSymbolAddress((void**)&fbh, g_fbh);
    cudaGetSymbolAddress((void**)&fbl, g_fbl);

    static bool attr_done = false;
    if (!attr_done) {
        cudaFuncSetAttribute(gemm_bf16x3<128, 0>,
                             cudaFuncAttributeMaxDynamicSharedMemorySize, 76800);
        cudaFuncSetAttribute(gemm_bf16x3<64, 1>,
                             cudaFuncAttributeMaxDynamicSharedMemorySize, 76800);
        cudaFuncSetAttribute(gemm_bf16x3<64, 2>,
                             cudaFuncAttributeMaxDynamicSharedMemorySize, 76800);
        attr_done = true;
    }
    const int smem128 = (2 * 2 * 128 * 40 + 2 * 2 * 32 * 136) * 2;  // 75776
    const int smem64  = (2 * 2 * 64 * 40 + 2 * 2 * 32 * 136) * 2;   // 55296

    // ---- weight splits ----
#define WSPLIT(src, off, M_, Mpad_, K_)                                        \
    wsplit_kernel<<<((Mpad_) * (K_) + 255) / 256, 256>>>(                      \
        src, wh + (off), wl + (off), M_, K_, (Mpad_) * (K_))
    WSPLIT(w2, OFF_W2, 192, 256, 1600);
    WSPLIT(w3, OFF_W3, 384, 384, 1728);
    WSPLIT(w4, OFF_W4, 256, 256, 3456);
    WSPLIT(w5, OFF_W5, 256, 256, 2304);
    WSPLIT(fw1, OFF_FW1, 4096, 4096, 4096);
    WSPLIT(fw2, OFF_FW2, 4096, 4096, 4096);
    WSPLIT(fw3, OFF_FW3, 1000, 1024, 4096);
#undef WSPLIT

    // conv1 + relu + pool -> act0 [256,64,16,16]
    conv1_pool_kernel<<<dim3(64, NIMG), 256>>>(x, w1, b1, act0);

    // conv2: 5x5 pad2, C=64 -> [256,192,16,16] -> pool -> act0
    {
        const int K = 1600, N = NIMG * 256;
        const long long total = (long long)K * N;
        im2col_split_kernel<<<(unsigned)((total + 255) / 256), 256>>>(
            act0, colh, coll, 64, 16, 16, 5, 2, 16, 16, N, total);
        gemm_bf16x3<128, 0><<<dim3(N / 128, 2), 256, smem128>>>(
            wh + OFF_W2, wl + OFF_W2, colh, coll, b2, act1, nullptr, nullptr,
            192, N, K, 256, 1);
        const long long pt = (long long)NIMG * 192 * 8 * 8;
        maxpool_kernel<<<(unsigned)((pt + 255) / 256), 256>>>(act1, act0, 16, 16, pt);
    }
    // conv3: 3x3 pad1, C=192 -> [256,384,8,8] in act1
    {
        const int K = 1728, N = NIMG * 64;
        const long long total = (long long)K * N;
        im2col_split_kernel<<<(unsigned)((total + 255) / 256), 256>>>(
            act0, colh, coll, 192, 8, 8, 3, 1, 8, 8, N, total);
        gemm_bf16x3<128, 0><<<dim3(N / 128, 3), 256, smem128>>>(
            wh + OFF_W3, wl + OFF_W3, colh, coll, b3, act1, nullptr, nullptr,
            384, N, K, 64, 1);
    }
    // conv4: 3x3 pad1, C=384 -> [256,256,8,8] in act0
    {
        const int K = 3456, N = NIMG * 64;
        const long long total = (long long)K * N;
        im2col_split_kernel<<<(unsigned)((total + 255) / 256), 256>>>(
            act1, colh, coll, 384, 8, 8, 3, 1, 8, 8, N, total);
        gemm_bf16x3<128, 0><<<dim3(N / 128, 2), 256, smem128>>>(
            wh + OFF_W4, wl + OFF_W4, colh, coll, b4, act0, nullptr, nullptr,
            256, N, K, 64, 1);
    }
    // conv5: 3x3 pad1, C=256 -> pool -> act0 [256][4096]
    {
        const int K = 2304, N = NIMG * 64;
        const long long total = (long long)K * N;
        im2col_split_kernel<<<(unsigned)((total + 255) / 256), 256>>>(
            act0, colh, coll, 256, 8, 8, 3, 1, 8, 8, N, total);
        gemm_bf16x3<128, 0><<<dim3(N / 128, 2), 256, smem128>>>(
            wh + OFF_W5, wl + OFF_W5, colh, coll, b5, act1, nullptr, nullptr,
            256, N, K, 64, 1);
        const long long pt = (long long)NIMG * 256 * 4 * 4;
        maxpool_kernel<<<(unsigned)((pt + 255) / 256), 256>>>(act1, act0, 8, 8, pt);
    }
    // fc input planes: act0 [256][4096] -> [4096][256] bf16 hi/lo
    tsplit_kernel<<<dim3(128, 8), dim3(32, 32)>>>(act0, fbh, fbl, 4096);

    const size_t FB = (size_t)4096 * 256;
    // fc1 -> planes slot1 (relu)
    gemm_bf16x3<64, 1><<<dim3(2, 64), 256, smem64>>>(
        wh + OFF_FW1, wl + OFF_FW1, fbh, fbl, fb1, nullptr,
        fbh + FB, fbl + FB, 4096, NIMG, 4096, 0, 1);
    // fc2 -> planes slot2 (relu)
    gemm_bf16x3<64, 1><<<dim3(2, 64), 256, smem64>>>(
        wh + OFF_FW2, wl + OFF_FW2, fbh + FB, fbl + FB, fb2, nullptr,
        fbh + 2 * FB, fbl + 2 * FB, 4096, NIMG, 4096, 0, 1);
    // fc3 -> fp32 d_out [256,1000]
    gemm_bf16x3<64, 2><<<dim3(2, 16), 256, smem64>>>(
        wh + OFF_FW3, wl + OFF_FW3, fbh + 2 * FB, fbl + 2 * FB, fb3, out,
        nullptr, nullptr, 1000, NIMG, 4096, 0, 0);
}

// round 5
// speedup vs baseline: 1.7697x; 1.0003x over previous
#include <cuda_runtime.h>
#include <cuda_bf16.h>
#include <cstdint>

// ---------------------------------------------------------------------------
// AlexNet (CIFAR) forward, B=256, fp32 I/O.
// Weights pre-split to padded bf16 hi/lo planes. All GEMM operands are bf16
// planes; mainloop = cp.async + ldmatrix + mma.sync (bf16x3, 3 passes).
// ---------------------------------------------------------------------------

#define NIMG 256

__device__ float g_act0[NIMG * 192 * 16 * 16];
__device__ float g_act1[NIMG * 192 * 16 * 16];
__device__ __nv_bfloat16 g_colh[1600 * 65536];
__device__ __nv_bfloat16 g_coll[1600 * 65536];
__device__ __nv_bfloat16 g_wh[40296448];
__device__ __nv_bfloat16 g_wl[40296448];
__device__ __nv_bfloat16 g_fbh[3 * 4096 * 256];
__device__ __nv_bfloat16 g_fbl[3 * 4096 * 256];

// weight plane offsets (elements), Mpad x K each
#define OFF_W2  0            // 256 x 1600
#define OFF_W3  409600       // 384 x 1728
#define OFF_W4  1073152      // 256 x 3456
#define OFF_W5  1957888      // 256 x 2304
#define OFF_FW1 2547712      // 4096 x 4096
#define OFF_FW2 19324928     // 4096 x 4096
#define OFF_FW3 36102144     // 1024 x 4096

// ---------------- helpers ----------------
__device__ __forceinline__ uint32_t smem_u32(const void* p) {
    return (uint32_t)__cvta_generic_to_shared(p);
}
__device__ __forceinline__ void cp16(void* dst, const void* src) {
    asm volatile("cp.async.cg.shared.global [%0], [%1], 16;\n"
                 :: "r"(smem_u32(dst)), "l"(src));
}
__device__ __forceinline__ void cp_commit() {
    asm volatile("cp.async.commit_group;\n");
}
template <int N>
__device__ __forceinline__ void cp_wait() {
    asm volatile("cp.async.wait_group %0;\n" :: "n"(N));
}
__device__ __forceinline__ void ldm_x4(uint32_t& r0, uint32_t& r1, uint32_t& r2,
                                       uint32_t& r3, uint32_t addr) {
    asm volatile("ldmatrix.sync.aligned.m8n8.x4.shared.b16 {%0,%1,%2,%3}, [%4];\n"
                 : "=r"(r0), "=r"(r1), "=r"(r2), "=r"(r3) : "r"(addr));
}
__device__ __forceinline__ void ldm_x2t(uint32_t& r0, uint32_t& r1, uint32_t addr) {
    asm volatile("ldmatrix.sync.aligned.m8n8.x2.trans.shared.b16 {%0,%1}, [%2];\n"
                 : "=r"(r0), "=r"(r1) : "r"(addr));
}
__device__ __forceinline__ void mma_bf16(float* d, const uint32_t* a, const uint32_t* b) {
    asm volatile(
        "mma.sync.aligned.m16n8k16.row.col.f32.bf16.bf16.f32 "
        "{%0,%1,%2,%3}, {%4,%5,%6,%7}, {%8,%9}, {%0,%1,%2,%3};\n"
        : "+f"(d[0]), "+f"(d[1]), "+f"(d[2]), "+f"(d[3])
        : "r"(a[0]), "r"(a[1]), "r"(a[2]), "r"(a[3]), "r"(b[0]), "r"(b[1]));
}
__device__ __forceinline__ void bsplit(float v, float& hi, float& lo) {
    hi = __bfloat162float(__float2bfloat16_rn(v));
    lo = v - hi;
}

// ---------------------------------------------------------------------------
// weight split: fp32 [M][K] -> bf16 hi/lo planes [Mpad][K], zero padded rows
// ---------------------------------------------------------------------------
__global__ __launch_bounds__(256) void wsplit_kernel(
    const float* __restrict__ w, __nv_bfloat16* __restrict__ wh,
    __nv_bfloat16* __restrict__ wl, int M, int K, int total) {
    int idx = blockIdx.x * 256 + threadIdx.x;
    if (idx >= total) return;
    const int m = idx / K;
    float v = (m < M) ? w[idx] : 0.0f;
    float h, l;
    bsplit(v, h, l);
    wh[idx] = __float2bfloat16_rn(h);
    wl[idx] = __float2bfloat16_rn(l);
}

// ---------------------------------------------------------------------------
// transpose+split: fp32 [256][K] -> bf16 planes [K][256]
// ---------------------------------------------------------------------------
__global__ void tsplit_kernel(const float* __restrict__ in,
                              __nv_bfloat16* __restrict__ oh,
                              __nv_bfloat16* __restrict__ ol, int K) {
    __shared__ float t[32][33];
    const int k0 = blockIdx.x * 32, n0 = blockIdx.y * 32;
    t[threadIdx.y][threadIdx.x] =
        in[(size_t)(n0 + threadIdx.y) * K + k0 + threadIdx.x];
    __syncthreads();
    const int k = k0 + threadIdx.y, n = n0 + threadIdx.x;
    float h, l;
    bsplit(t[threadIdx.x][threadIdx.y], h, l);
    oh[(size_t)k * 256 + n] = __float2bfloat16_rn(h);
    ol[(size_t)k * 256 + n] = __float2bfloat16_rn(l);
}

// ---------------------------------------------------------------------------
// conv1: 3x3 C3 pad1 32x32 -> relu -> maxpool2 -> [256,64,16,16]
// ---------------------------------------------------------------------------
__global__ __launch_bounds__(256) void conv1_pool_kernel(
    const float* __restrict__ x, const float* __restrict__ w,
    const float* __restrict__ b, float* __restrict__ out) {
    __shared__ float xs[3 * 32 * 32];
    __shared__ float ws[27];
    const int oc = blockIdx.x;
    const int n = blockIdx.y;
    const int tid = threadIdx.x;

    const float* xn = x + (long long)n * 3 * 32 * 32;
    for (int i = tid; i < 3 * 32 * 32; i += 256) xs[i] = xn[i];
    if (tid < 27) ws[tid] = w[oc * 27 + tid];
    __syncthreads();

    const float bias = b[oc];
    const int px = tid & 15, py = tid >> 4;
    float m = -1e30f;
#pragma unroll
    for (int dy = 0; dy < 2; dy++) {
#pragma unroll
        for (int dx = 0; dx < 2; dx++) {
            const int oy = 2 * py + dy, ox = 2 * px + dx;
            float sum = bias;
#pragma unroll
            for (int ci = 0; ci < 3; ci++) {
#pragma unroll
                for (int r = 0; r < 3; r++) {
                    const int iy = oy + r - 1;
                    if (iy < 0 || iy > 31) continue;
#pragma unroll
                    for (int s = 0; s < 3; s++) {
                        const int ix = ox + s - 1;
                        if (ix < 0 || ix > 31) continue;
                        sum += xs[ci * 1024 + iy * 32 + ix] * ws[ci * 9 + r * 3 + s];
                    }
                }
            }
            sum = fmaxf(sum, 0.0f);
            m = fmaxf(m, sum);
        }
    }
    out[(((long long)n * 64 + oc) * 16 + py) * 16 + px] = m;
}

// ---------------------------------------------------------------------------
// im2col with bf16 hi/lo split: colh/coll[k*N + n]
// ---------------------------------------------------------------------------
__global__ __launch_bounds__(256) void im2col_split_kernel(
    const float* __restrict__ in, __nv_bfloat16* __restrict__ colh,
    __nv_bfloat16* __restrict__ coll,
    int C, int H, int W, int R, int pad, int OH, int OW, int N, long long total) {
    long long idx = (long long)blockIdx.x * 256 + threadIdx.x;
    if (idx >= total) return;
    const int n = (int)(idx % N);
    const int k = (int)(idx / N);
    const int s = k % R;
    const int r = (k / R) % R;
    const int ci = k / (R * R);
    const int ox = n % OW;
    const int oy = (n / OW) % OH;
    const int img = n / (OW * OH);
    const int iy = oy + r - pad;
    const int ix = ox + s - pad;
    float v = 0.0f;
    if (iy >= 0 && iy < H && ix >= 0 && ix < W)
        v = in[(((long long)img * C + ci) * H + iy) * W + ix];
    float hi, lo;
    bsplit(v, hi, lo);
    colh[idx] = __float2bfloat16_rn(hi);
    coll[idx] = __float2bfloat16_rn(lo);
}

// ---------------------------------------------------------------------------
// maxpool 2x2 stride 2
// ---------------------------------------------------------------------------
__global__ __launch_bounds__(256) void maxpool_kernel(
    const float* __restrict__ in, float* __restrict__ out,
    int H, int W, long long total) {
    long long idx = (long long)blockIdx.x * 256 + threadIdx.x;
    if (idx >= total) return;
    const int OW = W >> 1, OH = H >> 1;
    const int x = (int)(idx % OW);
    const int y = (int)((idx / OW) % OH);
    const long long nc = idx / ((long long)OW * OH);
    const float* p = in + (nc * H + 2 * y) * W + 2 * x;
    out[idx] = fmaxf(fmaxf(p[0], p[1]), fmaxf(p[W], p[W + 1]));
}

// ---------------------------------------------------------------------------
// bf16x3 tensor-core GEMM, all-bf16 operands, 2-stage cp.async pipeline.
//   C[M,N] = A[M,K] @ B[K,N] + bias
//   A: bf16 planes [Mpad][K] (pre-split, padded -> unguarded loads)
//   B: bf16 planes [K][N]
//   EPI 0: fp32 NCHW via HW. EPI 1: bf16 planes out[m*N+n] (+relu).
//   EPI 2: fp32 out[n*M+m].
// Block BM x 128, BK=32, 8 warps; warp tile (BM/2) x 32 of m16n8k16.
// Requires K%32==0, N%128==0, KT>=2.
// ---------------------------------------------------------------------------
template <int BM, int EPI>
__global__ __launch_bounds__(256, 2) void gemm_bf16x3(
    const __nv_bfloat16* __restrict__ Ah, const __nv_bfloat16* __restrict__ Al,
    const __nv_bfloat16* __restrict__ Bh, const __nv_bfloat16* __restrict__ Bl,
    const float* __restrict__ bias, float* __restrict__ outf,
    __nv_bfloat16* __restrict__ outh, __nv_bfloat16* __restrict__ outl,
    int M, int N, int K, int HW, int relu) {
    constexpr int AST = 40;    // A smem row stride (bf16): 32 data + 8 pad (80B)
    constexpr int BST = 136;   // B smem row stride: 128 data + 8 pad (272B)
    constexpr int WTM = BM / 2, TM = WTM / 16, TN = 4;
    constexpr int NA = BM / 32;          // A cp16s per thread
    constexpr int LA = (BM == 128) ? 9 : 8;

    extern __shared__ __align__(16) __nv_bfloat16 smem[];
    __nv_bfloat16* As = smem;                       // [2][2][BM][AST]
    __nv_bfloat16* Bs = smem + 2 * 2 * BM * AST;    // [2][2][32][BST]

    const int tid = threadIdx.x, lane = tid & 31, warp = tid >> 5;
    const int g = lane >> 2, tg = lane & 3;
    const int warp_m = (warp >> 2) * WTM;
    const int warp_n = (warp & 3) * 32;
    const int m0 = blockIdx.y * BM, n0 = blockIdx.x * 128;
    const int KT = K / 32;

#define AIDX(st, p, row, col) ((((st)*2 + (p)) * BM + (row)) * AST + (col))
#define BIDX(st, p, row, col) ((((st)*2 + (p)) * 32 + (row)) * BST + (col))

#define LOADT(kt_, st_)                                                        \
    {                                                                          \
        const int kbase = (kt_)*32;                                            \
        _Pragma("unroll") for (int i = 0; i < NA; i++) {                       \
            const int c = tid + i * 256;                                       \
            const int p = c >> LA, rem = c & ((1 << LA) - 1);                  \
            const int row = rem >> 2, ch = (rem & 3) * 8;                      \
            const __nv_bfloat16* s =                                           \
                (p ? Al : Ah) + (size_t)(m0 + row) * K + kbase + ch;           \
            cp16(&As[AIDX(st_, p, row, ch)], s);                               \
        }                                                                      \
        _Pragma("unroll") for (int i = 0; i < 4; i++) {                        \
            const int c = tid + i * 256;                                       \
            const int p = c >> 9, rem = c & 511;                               \
            const int row = rem >> 4, ch = (rem & 15) * 8;                     \
            const __nv_bfloat16* s =                                           \
                (p ? Bl : Bh) + (size_t)(kbase + row) * N + n0 + ch;           \
            cp16(&Bs[BIDX(st_, p, row, ch)], s);                               \
        }                                                                      \
    }

    float acc[TM][TN][4];
#pragma unroll
    for (int i = 0; i < TM; i++)
#pragma unroll
        for (int j = 0; j < TN; j++)
#pragma unroll
            for (int e = 0; e < 4; e++) acc[i][j][e] = 0.0f;

    LOADT(0, 0); cp_commit();
    LOADT(1, 1); cp_commit();

    for (int kt = 0; kt < KT; kt++) {
        if (kt == KT - 1) { cp_wait<0>(); } else { cp_wait<1>(); }
        __syncthreads();
        const int st = kt & 1;
#pragma unroll
        for (int ks = 0; ks < 32; ks += 16) {
            uint32_t bh[TN][2], bl[TN][2];
#pragma unroll
            for (int ni = 0; ni < TN; ni++) {
                const int krow = ks + (lane & 15);
                const int ncol = warp_n + ni * 8;
                ldm_x2t(bh[ni][0], bh[ni][1], smem_u32(&Bs[BIDX(st, 0, krow, ncol)]));
                ldm_x2t(bl[ni][0], bl[ni][1], smem_u32(&Bs[BIDX(st, 1, krow, ncol)]));
            }
#pragma unroll
            for (int mi = 0; mi < TM; mi++) {
                const int mrow = warp_m + mi * 16 + (lane & 15);
                const int kcol = ks + (lane >> 4) * 8;
                uint32_t ah[4], al[4];
                ldm_x4(ah[0], ah[1], ah[2], ah[3], smem_u32(&As[AIDX(st, 0, mrow, kcol)]));
                ldm_x4(al[0], al[1], al[2], al[3], smem_u32(&As[AIDX(st, 1, mrow, kcol)]));
#pragma unroll
                for (int ni = 0; ni < TN; ni++) {
                    mma_bf16(acc[mi][ni], ah, bh[ni]);
                    mma_bf16(acc[mi][ni], al, bh[ni]);
                    mma_bf16(acc[mi][ni], ah, bl[ni]);
                }
            }
        }
        __syncthreads();
        if (kt + 2 < KT) { LOADT(kt + 2, st); cp_commit(); }
    }

    // ---- epilogue ----
#pragma unroll
    for (int mi = 0; mi < TM; mi++) {
#pragma unroll
        for (int ei = 0; ei < 2; ei++) {
            const int m = m0 + warp_m + mi * 16 + g + ei * 8;
            if (m >= M) continue;
            const float bv = bias[m];
#pragma unroll
            for (int ni = 0; ni < TN; ni++) {
#pragma unroll
                for (int ej = 0; ej < 2; ej++) {
                    const int n = n0 + warp_n + ni * 8 + 2 * tg + ej;
                    float v = acc[mi][ni][ei * 2 + ej] + bv;
                    if (relu) v = fmaxf(v, 0.0f);
                    if (EPI == 0) {
                        const int img = n / HW, hw = n - img * HW;
                        outf[((size_t)img * M + m) * HW + hw] = v;
                    } else if (EPI == 1) {
                        float h, l;
                        bsplit(v, h, l);
                        outh[(size_t)m * N + n] = __float2bfloat16_rn(h);
                        outl[(size_t)m * N + n] = __float2bfloat16_rn(l);
                    } else {
                        outf[(size_t)n * M + m] = v;
                    }
                }
            }
        }
    }
#undef LOADT
#undef AIDX
#undef BIDX
}

// ---------------------------------------------------------------------------
// Host launcher
// ---------------------------------------------------------------------------
extern "C" void kernel_launch(void* const* d_in, const int* in_sizes, int n_in,
                              void* d_out, int out_size) {
    const float* x  = (const float*)d_in[0];
    const float* w1 = (const float*)d_in[1];
    const float* b1 = (const float*)d_in[2];
    const float* w2 = (const float*)d_in[3];
    const float* b2 = (const float*)d_in[4];
    const float* w3 = (const float*)d_in[5];
    const float* b3 = (const float*)d_in[6];
    const float* w4 = (const float*)d_in[7];
    const float* b4 = (const float*)d_in[8];
    const float* w5 = (const float*)d_in[9];
    const float* b5 = (const float*)d_in[10];
    const float* fw1 = (const float*)d_in[11];
    const float* fb1 = (const float*)d_in[12];
    const float* fw2 = (const float*)d_in[13];
    const float* fb2 = (const float*)d_in[14];
    const float* fw3 = (const float*)d_in[15];
    const float* fb3 = (const float*)d_in[16];
    float* out = (float*)d_out;

    float *act0, *act1;
    __nv_bfloat16 *colh, *coll, *wh, *wl, *fbh, *fbl;
    cudaGetSymbolAddress((void**)&act0, g_act0);
    cudaGetSymbolAddress((void**)&act1, g_act1);
    cudaGetSymbolAddress((void**)&colh, g_colh);
    cudaGetSymbolAddress((void**)&coll, g_coll);
    cudaGetSymbolAddress((void**)&wh, g_wh);
    cudaGetSymbolAddress((void**)&wl, g_wl);
    cudaGetSymbolAddress((void**)&fbh, g_fbh);
    cudaGetSymbolAddress((void**)&fbl, g_fbl);

    static bool attr_done = false;
    if (!attr_done) {
        cudaFuncSetAttribute(gemm_bf16x3<128, 0>,
                             cudaFuncAttributeMaxDynamicSharedMemorySize, 76800);
        cudaFuncSetAttribute(gemm_bf16x3<64, 1>,
                             cudaFuncAttributeMaxDynamicSharedMemorySize, 76800);
        cudaFuncSetAttribute(gemm_bf16x3<64, 2>,
                             cudaFuncAttributeMaxDynamicSharedMemorySize, 76800);
        attr_done = true;
    }
    const int smem128 = (2 * 2 * 128 * 40 + 2 * 2 * 32 * 136) * 2;  // 75776
    const int smem64  = (2 * 2 * 64 * 40 + 2 * 2 * 32 * 136) * 2;   // 55296

    // ---- weight splits ----
#define WSPLIT(src, off, M_, Mpad_, K_)                                        \
    wsplit_kernel<<<((Mpad_) * (K_) + 255) / 256, 256>>>(                      \
        src, wh + (off), wl + (off), M_, K_, (Mpad_) * (K_))
    WSPLIT(w2, OFF_W2, 192, 256, 1600);
    WSPLIT(w3, OFF_W3, 384, 384, 1728);
    WSPLIT(w4, OFF_W4, 256, 256, 3456);
    WSPLIT(w5, OFF_W5, 256, 256, 2304);
    WSPLIT(fw1, OFF_FW1, 4096, 4096, 4096);
    WSPLIT(fw2, OFF_FW2, 4096, 4096, 4096);
    WSPLIT(fw3, OFF_FW3, 1000, 1024, 4096);
#undef WSPLIT

    // conv1 + relu + pool -> act0 [256,64,16,16]
    conv1_pool_kernel<<<dim3(64, NIMG), 256>>>(x, w1, b1, act0);

    // conv2: 5x5 pad2, C=64 -> [256,192,16,16] -> pool -> act0
    {
        const int K = 1600, N = NIMG * 256;
        const long long total = (long long)K * N;
        im2col_split_kernel<<<(unsigned)((total + 255) / 256), 256>>>(
            act0, colh, coll, 64, 16, 16, 5, 2, 16, 16, N, total);
        gemm_bf16x3<128, 0><<<dim3(N / 128, 2), 256, smem128>>>(
            wh + OFF_W2, wl + OFF_W2, colh, coll, b2, act1, nullptr, nullptr,
            192, N, K, 256, 1);
        const long long pt = (long long)NIMG * 192 * 8 * 8;
        maxpool_kernel<<<(unsigned)((pt + 255) / 256), 256>>>(act1, act0, 16, 16, pt);
    }
    // conv3: 3x3 pad1, C=192 -> [256,384,8,8] in act1
    {
        const int K = 1728, N = NIMG * 64;
        const long long total = (long long)K * N;
        im2col_split_kernel<<<(unsigned)((total + 255) / 256), 256>>>(
            act0, colh, coll, 192, 8, 8, 3, 1, 8, 8, N, total);
        gemm_bf16x3<128, 0><<<dim3(N / 128, 3), 256, smem128>>>(
            wh + OFF_W3, wl + OFF_W3, colh, coll, b3, act1, nullptr, nullptr,
            384, N, K, 64, 1);
    }
    // conv4: 3x3 pad1, C=384 -> [256,256,8,8] in act0
    {
        const int K = 3456, N = NIMG * 64;
        const long long total = (long long)K * N;
        im2col_split_kernel<<<(unsigned)((total + 255) / 256), 256>>>(
            act1, colh, coll, 384, 8, 8, 3, 1, 8, 8, N, total);
        gemm_bf16x3<128, 0><<<dim3(N / 128, 2), 256, smem128>>>(
            wh + OFF_W4, wl + OFF_W4, colh, coll, b4, act0, nullptr, nullptr,
            256, N, K, 64, 1);
    }
    // conv5: 3x3 pad1, C=256 -> pool -> act0 [256][4096]
    {
        const int K = 2304, N = NIMG * 64;
        const long long total = (long long)K * N;
        im2col_split_kernel<<<(unsigned)((total + 255) / 256), 256>>>(
            act0, colh, coll, 256, 8, 8, 3, 1, 8, 8, N, total);
        gemm_bf16x3<128, 0><<<dim3(N / 128, 2), 256, smem128>>>(
            wh + OFF_W5, wl + OFF_W5, colh, coll, b5, act1, nullptr, nullptr,
            256, N, K, 64, 1);
        const long long pt = (long long)NIMG * 256 * 4 * 4;
        maxpool_kernel<<<(unsigned)((pt + 255) / 256), 256>>>(act1, act0, 8, 8, pt);
    }
    // fc input planes: act0 [256][4096] -> [4096][256] bf16 hi/lo
    tsplit_kernel<<<dim3(128, 8), dim3(32, 32)>>>(act0, fbh, fbl, 4096);

    const size_t FB = (size_t)4096 * 256;
    // fc1 -> planes slot1 (relu)
    gemm_bf16x3<64, 1><<<dim3(2, 64), 256, smem64>>>(
        wh + OFF_FW1, wl + OFF_FW1, fbh, fbl, fb1, nullptr,
        fbh + FB, fbl + FB, 4096, NIMG, 4096, 0, 1);
    // fc2 -> planes slot2 (relu)
    gemm_bf16x3<64, 1><<<dim3(2, 64), 256, smem64>>>(
        wh + OFF_FW2, wl + OFF_FW2, fbh + FB, fbl + FB, fb2, nullptr,
        fbh + 2 * FB, fbl + 2 * FB, 4096, NIMG, 4096, 0, 1);
    // fc3 -> fp32 d_out [256,1000]
    gemm_bf16x3<64, 2><<<dim3(2, 16), 256, smem64>>>(
        wh + OFF_FW3, wl + OFF_FW3, fbh + 2 * FB, fbl + 2 * FB, fb3, out,
        nullptr, nullptr, 1000, NIMG, 4096, 0, 0);
}